// round 2
// baseline (speedup 1.0000x reference)
#include <cuda_runtime.h>
#include <cuda_bf16.h>
#include <cstdint>
#include <cfloat>

#define BB   8
#define NN   2048
#define DIN  32
#define DH   64
#define NW   (NN/16)          // 128 packed 2-bit label words per row
#define XWS  (BB*NN*DH)       // per-relation stride in g_xw

// ---------------- device scratch (no allocs allowed) ----------------
__device__ uint32_t g_relp[BB*NN*NW];     // packed relation labels (2 bit), 8.4 MB
__device__ float    g_xw [3*XWS];         // per-relation x@W (tf32-rounded)
__device__ float    g_h  [BB*NN*DH];      // layer output (post relu/norm), pre-BN
__device__ float    g_hn [BB*NN*DH];      // post-BN (input to next layer)
__device__ float    g_mean[NN];
__device__ float    g_rstd[NN];
__device__ float    g_pmax[3*8*BB*DH];    // [layer][slab][b][d]

// ---------------- helpers ----------------
__device__ __forceinline__ float to_tf32(float v) {
    uint32_t t; asm("cvt.rna.tf32.f32 %0, %1;" : "=r"(t) : "f"(v));
    return __uint_as_float(t);
}

__device__ __forceinline__ void mma_tf32_k8(float c[4],
                                            uint32_t a0, uint32_t a1, uint32_t a2, uint32_t a3,
                                            uint32_t b0, uint32_t b1) {
    asm volatile(
        "mma.sync.aligned.m16n8k8.row.col.f32.tf32.tf32.f32 "
        "{%0,%1,%2,%3}, {%4,%5,%6,%7}, {%8,%9}, {%0,%1,%2,%3};\n"
        : "+f"(c[0]), "+f"(c[1]), "+f"(c[2]), "+f"(c[3])
        : "r"(a0), "r"(a1), "r"(a2), "r"(a3), "r"(b0), "r"(b1));
}

// ---------------- pack relation labels to 2 bits ----------------
__global__ void pack_rel_kernel(const int* __restrict__ rel) {
    int idx = blockIdx.x * blockDim.x + threadIdx.x;   // word index
    if (idx >= BB*NN*NW) return;
    const int4* p = (const int4*)(rel + (size_t)idx * 16);
    uint32_t wv = 0;
    #pragma unroll
    for (int q = 0; q < 4; q++) {
        int4 v = p[q];
        wv |= (uint32_t)(v.x & 3) << (8*q + 0);
        wv |= (uint32_t)(v.y & 3) << (8*q + 2);
        wv |= (uint32_t)(v.z & 3) << (8*q + 4);
        wv |= (uint32_t)(v.w & 3) << (8*q + 6);
    }
    g_relp[idx] = wv;
}

// ---------------- xw_r = x @ W_first[r], tf32-rounded ----------------
__global__ void xw_first_kernel(const float* __restrict__ x, const float* __restrict__ w) {
    __shared__ float xs[DIN];
    int row = blockIdx.x;                  // b*NN + j
    int t = threadIdx.x;                   // 0..191
    if (t < DIN) xs[t] = x[(size_t)row*DIN + t];
    __syncthreads();
    int r = t >> 6, d = t & 63;
    float acc = 0.f;
    #pragma unroll
    for (int k = 0; k < DIN; k++)
        acc = fmaf(xs[k], __ldg(&w[(r*DIN + k)*DH + d]), acc);
    g_xw[(size_t)r*XWS + (size_t)row*DH + d] = to_tf32(acc);
}

// ---------------- xw = hn @ W[0]  (64x64), tf32-rounded ----------------
__global__ void hw_kernel(const float* __restrict__ w) {
    __shared__ float ws[DH*DH];            // 16 KB
    __shared__ float hs[4][DH];
    int t = threadIdx.x;
    for (int idx = t; idx < DH*DH/4; idx += 256)
        ((float4*)ws)[idx] = ((const float4*)w)[idx];
    int lr = t >> 6, d = t & 63;
    int row = blockIdx.x*4 + lr;
    hs[lr][d] = g_hn[(size_t)row*DH + d];
    __syncthreads();
    float acc = 0.f;
    #pragma unroll
    for (int k = 0; k < DH; k++)
        acc = fmaf(hs[lr][k], ws[k*DH + d], acc);
    g_xw[(size_t)row*DH + d] = to_tf32(acc);
}

// ---------------- masked aggregation GEMM + bias + L2 norm (+ReLU) ----------------
// grid: BB*16 (one CTA per (b, 128-row tile)); block 256 = 8 warps, each m16 x n64.
// NREL=3: masks (label == r+1); NREL=1: mask (label != 0) i.e. adj.
template<int NREL, bool RELU>
__global__ void agg_kernel(const float* __restrict__ bias) {
    extern __shared__ float Bs[];          // [NREL][64][72]
    const int b  = blockIdx.x >> 4;
    const int i0 = (blockIdx.x & 15) << 7;
    const int t = threadIdx.x;
    const int w = t >> 5, lane = t & 31, g = lane >> 2, tig = lane & 3;

    const int iA = i0 + w*16 + g;          // local row within batch
    const uint32_t* rpA = g_relp + (size_t)(b*NN + iA) * NW;
    const uint32_t* rpB = rpA + 8*NW;      // row iA+8

    float acc[8][4];
    #pragma unroll
    for (int nt = 0; nt < 8; nt++)
        #pragma unroll
        for (int q = 0; q < 4; q++) acc[nt][q] = 0.f;

    const uint32_t ONE = 0x3F800000u;

    for (int k0 = 0; k0 < NN; k0 += 64) {
        uint4 LA = *(const uint4*)(rpA + (k0 >> 4));
        uint4 LB = *(const uint4*)(rpB + (k0 >> 4));
        uint32_t wA[4] = {LA.x, LA.y, LA.z, LA.w};
        uint32_t wB[4] = {LB.x, LB.y, LB.z, LB.w};

        __syncthreads();
        // stage B chunk: [NREL][64 k][64 d] -> smem stride 72
        #pragma unroll
        for (int s = 0; s < NREL*4; s++) {
            int it  = s*256 + t;               // < NREL*1024
            int rel = it >> 10;
            int rem = it & 1023;
            int kk  = rem >> 4, c4 = rem & 15;
            float4 v = *(const float4*)(g_xw + (size_t)rel*XWS
                                        + (size_t)(b*NN + k0 + kk)*DH + c4*4);
            float* dst = Bs + (rel*64 + kk)*72 + c4*4;
            dst[0]=v.x; dst[1]=v.y; dst[2]=v.z; dst[3]=v.w;
        }
        __syncthreads();

        #pragma unroll
        for (int s8 = 0; s8 < 8; s8++) {
            const int wi   = s8 >> 1;
            const int base = 16*(s8 & 1) + 2*tig;
            uint32_t labA0 = (wA[wi] >> base) & 3;
            uint32_t labA1 = (wA[wi] >> (base + 8)) & 3;
            uint32_t labB0 = (wB[wi] >> base) & 3;
            uint32_t labB1 = (wB[wi] >> (base + 8)) & 3;
            #pragma unroll
            for (int r = 0; r < NREL; r++) {
                uint32_t a0, a1, a2, a3;
                if (NREL == 1) {
                    a0 = labA0 ? ONE : 0u; a1 = labB0 ? ONE : 0u;
                    a2 = labA1 ? ONE : 0u; a3 = labB1 ? ONE : 0u;
                } else {
                    a0 = (labA0 == (uint32_t)(r+1)) ? ONE : 0u;
                    a1 = (labB0 == (uint32_t)(r+1)) ? ONE : 0u;
                    a2 = (labA1 == (uint32_t)(r+1)) ? ONE : 0u;
                    a3 = (labB1 == (uint32_t)(r+1)) ? ONE : 0u;
                }
                const float* bp0 = Bs + (r*64 + s8*8 + tig) * 72;
                const float* bp1 = bp0 + 4*72;
                #pragma unroll
                for (int nt = 0; nt < 8; nt++) {
                    uint32_t b0 = __float_as_uint(bp0[nt*8 + g]);
                    uint32_t b1 = __float_as_uint(bp1[nt*8 + g]);
                    mma_tf32_k8(acc[nt], a0, a1, a2, a3, b0, b1);
                }
            }
        }
    }

    // epilogue: bias, L2 normalize over d (row sums via intra-quad butterfly), relu
    float s0 = 0.f, s1 = 0.f;
    #pragma unroll
    for (int nt = 0; nt < 8; nt++) {
        float bc0 = __ldg(&bias[nt*8 + 2*tig]);
        float bc1 = __ldg(&bias[nt*8 + 2*tig + 1]);
        acc[nt][0] += bc0; acc[nt][1] += bc1;
        acc[nt][2] += bc0; acc[nt][3] += bc1;
        s0 += acc[nt][0]*acc[nt][0] + acc[nt][1]*acc[nt][1];
        s1 += acc[nt][2]*acc[nt][2] + acc[nt][3]*acc[nt][3];
    }
    s0 += __shfl_xor_sync(0xffffffffu, s0, 1);
    s0 += __shfl_xor_sync(0xffffffffu, s0, 2);
    s1 += __shfl_xor_sync(0xffffffffu, s1, 1);
    s1 += __shfl_xor_sync(0xffffffffu, s1, 2);
    float sc0 = 1.f / fmaxf(sqrtf(s0), 1e-12f);
    float sc1 = 1.f / fmaxf(sqrtf(s1), 1e-12f);

    float* outA = g_h + (size_t)(b*NN + iA)*DH;
    float* outB = outA + 8*DH;
    #pragma unroll
    for (int nt = 0; nt < 8; nt++) {
        float y0 = acc[nt][0]*sc0, y1 = acc[nt][1]*sc0;
        float y2 = acc[nt][2]*sc1, y3 = acc[nt][3]*sc1;
        if (RELU) {
            y0 = fmaxf(y0, 0.f); y1 = fmaxf(y1, 0.f);
            y2 = fmaxf(y2, 0.f); y3 = fmaxf(y3, 0.f);
        }
        *(float2*)(outA + nt*8 + 2*tig) = make_float2(y0, y1);
        *(float2*)(outB + nt*8 + 2*tig) = make_float2(y2, y3);
    }
}

// ---------------- BatchNorm1d(N) training-mode stats per node index ----------------
__global__ void bn_stats_kernel() {
    const int i = blockIdx.x;
    const int t = threadIdx.x;
    // 512 values: (b,d), idx = t and t+256
    float v0 = g_h[(size_t)((t>>6)*NN + i)*DH + (t & 63)];
    int t2 = t + 256;
    float v1 = g_h[(size_t)((t2>>6)*NN + i)*DH + (t2 & 63)];
    float s = v0 + v1;
    float q = v0*v0 + v1*v1;
    #pragma unroll
    for (int off = 16; off > 0; off >>= 1) {
        s += __shfl_down_sync(0xffffffffu, s, off);
        q += __shfl_down_sync(0xffffffffu, q, off);
    }
    __shared__ float ss[8], qq[8];
    int wid = t >> 5, lane = t & 31;
    if (lane == 0) { ss[wid] = s; qq[wid] = q; }
    __syncthreads();
    if (t == 0) {
        float S = 0.f, Q = 0.f;
        #pragma unroll
        for (int k = 0; k < 8; k++) { S += ss[k]; Q += qq[k]; }
        float m = S * (1.f/512.f);
        float var = Q * (1.f/512.f) - m*m;
        g_mean[i] = m;
        g_rstd[i] = rsqrtf(var + 1e-5f);
    }
}

// ---------------- BN apply (optional) + partial max over 256-row slabs ----------------
template<bool BN>
__global__ void bn_apply_max_kernel(int L) {
    const int b    = blockIdx.x >> 3;
    const int slab = blockIdx.x & 7;
    const int t = threadIdx.x;
    const int d = t & 63, rg = t >> 6;
    float mx = -FLT_MAX;
    #pragma unroll 4
    for (int m = 0; m < 64; m++) {
        int i = slab*256 + m*4 + rg;
        float v = g_h[(size_t)(b*NN + i)*DH + d];
        if (BN) {
            v = (v - g_mean[i]) * g_rstd[i];
            g_hn[(size_t)(b*NN + i)*DH + d] = v;
        }
        mx = fmaxf(mx, v);
    }
    __shared__ float red[4][DH];
    red[rg][d] = mx;
    __syncthreads();
    if (rg == 0) {
        mx = fmaxf(fmaxf(red[0][d], red[1][d]), fmaxf(red[2][d], red[3][d]));
        g_pmax[((L*8 + slab)*BB + b)*DH + d] = mx;
    }
}

// ---------------- finalize: max-reduce slabs, concat, final linear ----------------
__global__ void finalize_kernel(const float* __restrict__ w_map,
                                const float* __restrict__ b_map,
                                float* __restrict__ out) {
    __shared__ float os[BB][192];
    int t = threadIdx.x;
    for (int idx = t; idx < BB*192; idx += 256) {
        int b = idx / 192, c = idx % 192;
        int l = c >> 6, d = c & 63;
        float m = -FLT_MAX;
        #pragma unroll
        for (int s = 0; s < 8; s++)
            m = fmaxf(m, g_pmax[((l*8 + s)*BB + b)*DH + d]);
        os[b][c] = m;
        out[idx] = m;                     // output block: [8][192]
    }
    __syncthreads();
    for (int idx = t; idx < BB*DH; idx += 256) {
        int b = idx >> 6, e = idx & 63;
        float a = b_map[e];
        #pragma unroll 4
        for (int k = 0; k < 192; k++)
            a = fmaf(os[b][k], w_map[k*DH + e], a);
        out[BB*192 + idx] = a;            // ypred block: [8][64]
    }
}

// ---------------- launch ----------------
extern "C" void kernel_launch(void* const* d_in, const int* in_sizes, int n_in,
                              void* d_out, int out_size) {
    const float* x       = (const float*)d_in[0];
    const int*   rel     = (const int*)  d_in[1];
    // d_in[2] = adj (unused; derivable from relation)
    const float* w_first = (const float*)d_in[3];
    const float* b_first = (const float*)d_in[4];
    const float* w_block = (const float*)d_in[5];
    const float* b_block = (const float*)d_in[6];
    const float* w_last  = (const float*)d_in[7];
    const float* b_last  = (const float*)d_in[8];
    const float* w_map   = (const float*)d_in[9];
    const float* b_map   = (const float*)d_in[10];
    float* out = (float*)d_out;

    const int smem3 = 3*64*72*4;   // 55296 B
    const int smem1 = 1*64*72*4;   // 18432 B
    cudaFuncSetAttribute(agg_kernel<3,true>,  cudaFuncAttributeMaxDynamicSharedMemorySize, smem3);
    cudaFuncSetAttribute(agg_kernel<1,true>,  cudaFuncAttributeMaxDynamicSharedMemorySize, smem1);
    cudaFuncSetAttribute(agg_kernel<1,false>, cudaFuncAttributeMaxDynamicSharedMemorySize, smem1);

    pack_rel_kernel<<<(BB*NN*NW + 255)/256, 256>>>(rel);
    xw_first_kernel<<<BB*NN, 192>>>(x, w_first);

    // layer 1
    agg_kernel<3,true><<<BB*16, 256, smem3>>>(b_first);
    bn_stats_kernel<<<NN, 256>>>();
    bn_apply_max_kernel<true><<<BB*8, 256>>>(0);

    // layer 2
    hw_kernel<<<BB*NN/4, 256>>>(w_block);
    agg_kernel<1,true><<<BB*16, 256, smem1>>>(b_block);
    bn_stats_kernel<<<NN, 256>>>();
    bn_apply_max_kernel<true><<<BB*8, 256>>>(1);

    // layer 3 (conv_last: no relu, no BN)
    hw_kernel<<<BB*NN/4, 256>>>(w_last);
    agg_kernel<1,false><<<BB*16, 256, smem1>>>(b_last);
    bn_apply_max_kernel<false><<<BB*8, 256>>>(2);

    finalize_kernel<<<1, 256>>>(w_map, b_map, out);
}

// round 3
// speedup vs baseline: 1.1426x; 1.1426x over previous
#include <cuda_runtime.h>
#include <cuda_bf16.h>
#include <cstdint>
#include <cfloat>

#define BB   8
#define NN   2048
#define DIN  32
#define DH   64
#define NW   (NN/16)          // 128 packed 2-bit label words per row
#define XWS  (BB*NN*DH)       // per-relation stride in g_xw

// ---------------- device scratch (no allocs allowed) ----------------
__device__ uint32_t g_relp[BB*NN*NW];     // packed relation labels (2 bit), 8.4 MB
__device__ float    g_xw [3*XWS];         // per-relation x@W, tf32-rounded, d-PERMUTED
__device__ float    g_h  [BB*NN*DH];      // layer output (post relu/norm), pre-BN
__device__ float    g_hn [BB*NN*DH];      // post-BN (input to next layer)
__device__ float    g_mean[NN];
__device__ float    g_rstd[NN];
__device__ float    g_pmax[3*8*BB*DH];    // [layer][slab][b][d]

// d-axis permutation applied to g_xw so B-fragments are LDS.128-contiguous:
// smem float p at row k <-> original column c with perm(c) = p
__device__ __forceinline__ int perm_d(int d) { return ((d & 7) << 3) | (d >> 3); }
// per-row 16B-chunk XOR swizzle (values {0,1,4,5}) for bank-conflict freedom
__device__ __forceinline__ int swz(int row) { return (row & 1) | ((row & 2) << 1); }

// ---------------- helpers ----------------
__device__ __forceinline__ float to_tf32(float v) {
    uint32_t t; asm("cvt.rna.tf32.f32 %0, %1;" : "=r"(t) : "f"(v));
    return __uint_as_float(t);
}

__device__ __forceinline__ void mma_tf32_k8(float c[4],
                                            uint32_t a0, uint32_t a1, uint32_t a2, uint32_t a3,
                                            uint32_t b0, uint32_t b1) {
    asm volatile(
        "mma.sync.aligned.m16n8k8.row.col.f32.tf32.tf32.f32 "
        "{%0,%1,%2,%3}, {%4,%5,%6,%7}, {%8,%9}, {%0,%1,%2,%3};\n"
        : "+f"(c[0]), "+f"(c[1]), "+f"(c[2]), "+f"(c[3])
        : "r"(a0), "r"(a1), "r"(a2), "r"(a3), "r"(b0), "r"(b1));
}

__device__ __forceinline__ void cp_async16(uint32_t dst, const void* src) {
    asm volatile("cp.async.cg.shared.global [%0], [%1], 16;\n"
                 :: "r"(dst), "l"(src) : "memory");
}
__device__ __forceinline__ void cp_commit() {
    asm volatile("cp.async.commit_group;\n" ::: "memory");
}
template<int N>
__device__ __forceinline__ void cp_wait() {
    asm volatile("cp.async.wait_group %0;\n" :: "n"(N) : "memory");
}

// ---------------- pack relation labels to 2 bits ----------------
__global__ void pack_rel_kernel(const int* __restrict__ rel) {
    int idx = blockIdx.x * blockDim.x + threadIdx.x;   // word index
    if (idx >= BB*NN*NW) return;
    const int4* p = (const int4*)(rel + (size_t)idx * 16);
    uint32_t wv = 0;
    #pragma unroll
    for (int q = 0; q < 4; q++) {
        int4 v = p[q];
        wv |= (uint32_t)(v.x & 3) << (8*q + 0);
        wv |= (uint32_t)(v.y & 3) << (8*q + 2);
        wv |= (uint32_t)(v.z & 3) << (8*q + 4);
        wv |= (uint32_t)(v.w & 3) << (8*q + 6);
    }
    g_relp[idx] = wv;
}

// ---------------- xw_r = x @ W_first[r], tf32, d-permuted; 32 rows/block ----------------
__global__ void xw_first_kernel(const float* __restrict__ x, const float* __restrict__ w) {
    __shared__ float ws[3*DIN*DH];   // 24 KB
    __shared__ float xs[32][DIN];    // 4 KB
    const int t = threadIdx.x;       // 192 threads
    const int row0 = blockIdx.x * 32;
    for (int i = t; i < 3*DIN*DH; i += 192) ws[i] = w[i];
    for (int i = t; i < 32*DIN; i += 192)
        xs[i >> 5][i & 31] = x[(size_t)row0*DIN + i];
    __syncthreads();
    const int r = t >> 6, d = t & 63;
    const int pd = perm_d(d);
    #pragma unroll 4
    for (int rr = 0; rr < 32; rr++) {
        float acc = 0.f;
        #pragma unroll
        for (int k = 0; k < DIN; k++)
            acc = fmaf(xs[rr][k], ws[(r*DIN + k)*DH + d], acc);
        g_xw[(size_t)r*XWS + (size_t)(row0 + rr)*DH + pd] = to_tf32(acc);
    }
}

// ---------------- xw = hn @ W[0]  (64x64), tf32, d-permuted ----------------
__global__ void hw_kernel(const float* __restrict__ w) {
    __shared__ float ws[DH*DH];            // 16 KB
    __shared__ float hs[4][DH];
    int t = threadIdx.x;
    for (int idx = t; idx < DH*DH/4; idx += 256)
        ((float4*)ws)[idx] = ((const float4*)w)[idx];
    int lr = t >> 6, d = t & 63;
    int row = blockIdx.x*4 + lr;
    hs[lr][d] = g_hn[(size_t)row*DH + d];
    __syncthreads();
    float acc = 0.f;
    #pragma unroll
    for (int k = 0; k < DH; k++)
        acc = fmaf(hs[lr][k], ws[k*DH + d], acc);
    g_xw[(size_t)row*DH + perm_d(d)] = to_tf32(acc);
}

// ---------------- masked aggregation GEMM + bias + L2 norm (+ReLU) ----------------
// grid: BB*16 (one CTA per (b, 128-row tile)); block 256 = 8 warps, each m16 x n64.
// Double-buffered cp.async staging; swizzled smem; LDS.128 B-fragments.
template<int NREL, bool RELU>
__global__ void agg_kernel(const float* __restrict__ bias) {
    extern __shared__ float Bs[];          // [2][NREL][64 rows][64 floats]
    const uint32_t sbase = (uint32_t)__cvta_generic_to_shared(Bs);
    const int BUFF = NREL * 64 * 64;       // floats per buffer

    const int b  = blockIdx.x >> 4;
    const int i0 = (blockIdx.x & 15) << 7;
    const int t = threadIdx.x;
    const int w = t >> 5, lane = t & 31, g = lane >> 2, tig = lane & 3;

    const int iA = i0 + w*16 + g;
    const uint32_t* rpA = g_relp + (size_t)(b*NN + iA) * NW;
    const uint32_t* rpB = rpA + 8*NW;

    // staging decomposition for this thread (constant across chunks)
    int st_rel[NREL*4], st_kk[NREL*4];
    uint32_t st_dst[NREL*4];
    const float* st_src[NREL*4];
    #pragma unroll
    for (int s = 0; s < NREL*4; s++) {
        int it  = s*256 + t;
        int rel = it >> 10;
        int rem = it & 1023;
        int kk  = rem >> 4, c4 = rem & 15;
        st_rel[s] = rel; st_kk[s] = kk;
        st_dst[s] = sbase + (uint32_t)((rel*4096 + kk*64 + ((c4 ^ swz(kk & 3)) << 2)) << 2);
        st_src[s] = g_xw + (size_t)rel*XWS + (size_t)(b*NN + kk)*DH + (c4 << 2);
    }

    float acc[8][4];
    #pragma unroll
    for (int nt = 0; nt < 8; nt++)
        #pragma unroll
        for (int q = 0; q < 4; q++) acc[nt][q] = 0.f;

    const uint32_t ONE = 0x3F800000u;

    // prologue: stage chunk 0 into buffer 0; preload labels for chunk 0
    #pragma unroll
    for (int s = 0; s < NREL*4; s++)
        cp_async16(st_dst[s], st_src[s]);
    cp_commit();
    uint4 LA = *(const uint4*)(rpA);
    uint4 LB = *(const uint4*)(rpB);

    for (int c = 0; c < 32; c++) {
        const int cb = c & 1;
        if (c + 1 < 32) {
            const uint32_t doff = (uint32_t)(((c + 1) & 1) * BUFF) << 2;
            const size_t goff = (size_t)(c + 1) * 64 * DH;
            #pragma unroll
            for (int s = 0; s < NREL*4; s++)
                cp_async16(st_dst[s] + doff, st_src[s] + goff);
            cp_commit();
            cp_wait<1>();
        } else {
            cp_wait<0>();
        }
        __syncthreads();

        uint32_t wA[4] = {LA.x, LA.y, LA.z, LA.w};
        uint32_t wB[4] = {LB.x, LB.y, LB.z, LB.w};
        if (c + 1 < 32) {
            LA = *(const uint4*)(rpA + (c + 1) * 4);
            LB = *(const uint4*)(rpB + (c + 1) * 4);
        }

        const float* bufp = Bs + cb * BUFF;
        const int sw = swz(tig);
        const int ch0 = (2*g) ^ sw, ch1 = (2*g + 1) ^ sw;

        #pragma unroll
        for (int s8 = 0; s8 < 8; s8++) {
            const int wi   = s8 >> 1;
            const int base = 16*(s8 & 1) + 2*tig;
            uint32_t labA0 = (wA[wi] >> base) & 3;
            uint32_t labA1 = (wA[wi] >> (base + 8)) & 3;
            uint32_t labB0 = (wB[wi] >> base) & 3;
            uint32_t labB1 = (wB[wi] >> (base + 8)) & 3;
            const int row0 = s8*8 + tig;
            #pragma unroll
            for (int r = 0; r < NREL; r++) {
                uint32_t a0, a1, a2, a3;
                if (NREL == 1) {
                    a0 = labA0 ? ONE : 0u; a1 = labB0 ? ONE : 0u;
                    a2 = labA1 ? ONE : 0u; a3 = labB1 ? ONE : 0u;
                } else {
                    a0 = (labA0 == (uint32_t)(r+1)) ? ONE : 0u;
                    a1 = (labB0 == (uint32_t)(r+1)) ? ONE : 0u;
                    a2 = (labA1 == (uint32_t)(r+1)) ? ONE : 0u;
                    a3 = (labB1 == (uint32_t)(r+1)) ? ONE : 0u;
                }
                const float* rb = bufp + r*4096;
                float4 B0a = *(const float4*)(rb + row0*64       + (ch0 << 2));
                float4 B0b = *(const float4*)(rb + row0*64       + (ch1 << 2));
                float4 B1a = *(const float4*)(rb + (row0+4)*64   + (ch0 << 2));
                float4 B1b = *(const float4*)(rb + (row0+4)*64   + (ch1 << 2));
                const float b0v[8] = {B0a.x,B0a.y,B0a.z,B0a.w, B0b.x,B0b.y,B0b.z,B0b.w};
                const float b1v[8] = {B1a.x,B1a.y,B1a.z,B1a.w, B1b.x,B1b.y,B1b.z,B1b.w};
                #pragma unroll
                for (int nt = 0; nt < 8; nt++)
                    mma_tf32_k8(acc[nt], a0, a1, a2, a3,
                                __float_as_uint(b0v[nt]), __float_as_uint(b1v[nt]));
            }
        }
        __syncthreads();
    }

    // epilogue: bias, L2 normalize over d (intra-quad butterfly), relu
    float s0 = 0.f, s1 = 0.f;
    #pragma unroll
    for (int nt = 0; nt < 8; nt++) {
        float bc0 = __ldg(&bias[nt*8 + 2*tig]);
        float bc1 = __ldg(&bias[nt*8 + 2*tig + 1]);
        acc[nt][0] += bc0; acc[nt][1] += bc1;
        acc[nt][2] += bc0; acc[nt][3] += bc1;
        s0 += acc[nt][0]*acc[nt][0] + acc[nt][1]*acc[nt][1];
        s1 += acc[nt][2]*acc[nt][2] + acc[nt][3]*acc[nt][3];
    }
    s0 += __shfl_xor_sync(0xffffffffu, s0, 1);
    s0 += __shfl_xor_sync(0xffffffffu, s0, 2);
    s1 += __shfl_xor_sync(0xffffffffu, s1, 1);
    s1 += __shfl_xor_sync(0xffffffffu, s1, 2);
    float sc0 = 1.f / fmaxf(sqrtf(s0), 1e-12f);
    float sc1 = 1.f / fmaxf(sqrtf(s1), 1e-12f);

    float* outA = g_h + (size_t)(b*NN + iA)*DH;
    float* outB = outA + 8*DH;
    #pragma unroll
    for (int nt = 0; nt < 8; nt++) {
        float y0 = acc[nt][0]*sc0, y1 = acc[nt][1]*sc0;
        float y2 = acc[nt][2]*sc1, y3 = acc[nt][3]*sc1;
        if (RELU) {
            y0 = fmaxf(y0, 0.f); y1 = fmaxf(y1, 0.f);
            y2 = fmaxf(y2, 0.f); y3 = fmaxf(y3, 0.f);
        }
        *(float2*)(outA + nt*8 + 2*tig) = make_float2(y0, y1);
        *(float2*)(outB + nt*8 + 2*tig) = make_float2(y2, y3);
    }
}

// ---------------- BatchNorm1d(N) training-mode stats per node index ----------------
__global__ void bn_stats_kernel() {
    const int i = blockIdx.x;
    const int t = threadIdx.x;
    float v0 = g_h[(size_t)((t>>6)*NN + i)*DH + (t & 63)];
    int t2 = t + 256;
    float v1 = g_h[(size_t)((t2>>6)*NN + i)*DH + (t2 & 63)];
    float s = v0 + v1;
    float q = v0*v0 + v1*v1;
    #pragma unroll
    for (int off = 16; off > 0; off >>= 1) {
        s += __shfl_down_sync(0xffffffffu, s, off);
        q += __shfl_down_sync(0xffffffffu, q, off);
    }
    __shared__ float ss[8], qq[8];
    int wid = t >> 5, lane = t & 31;
    if (lane == 0) { ss[wid] = s; qq[wid] = q; }
    __syncthreads();
    if (t == 0) {
        float S = 0.f, Q = 0.f;
        #pragma unroll
        for (int k = 0; k < 8; k++) { S += ss[k]; Q += qq[k]; }
        float m = S * (1.f/512.f);
        float var = Q * (1.f/512.f) - m*m;
        g_mean[i] = m;
        g_rstd[i] = rsqrtf(var + 1e-5f);
    }
}

// ---------------- BN apply (optional) + partial max over 256-row slabs ----------------
template<bool BN>
__global__ void bn_apply_max_kernel(int L) {
    const int b    = blockIdx.x >> 3;
    const int slab = blockIdx.x & 7;
    const int t = threadIdx.x;
    const int d = t & 63, rg = t >> 6;
    float mx = -FLT_MAX;
    #pragma unroll 4
    for (int m = 0; m < 64; m++) {
        int i = slab*256 + m*4 + rg;
        float v = g_h[(size_t)(b*NN + i)*DH + d];
        if (BN) {
            v = (v - g_mean[i]) * g_rstd[i];
            g_hn[(size_t)(b*NN + i)*DH + d] = v;
        }
        mx = fmaxf(mx, v);
    }
    __shared__ float red[4][DH];
    red[rg][d] = mx;
    __syncthreads();
    if (rg == 0) {
        mx = fmaxf(fmaxf(red[0][d], red[1][d]), fmaxf(red[2][d], red[3][d]));
        g_pmax[((L*8 + slab)*BB + b)*DH + d] = mx;
    }
}

// ---------------- finalize: max-reduce slabs, concat, final linear ----------------
__global__ void finalize_kernel(const float* __restrict__ w_map,
                                const float* __restrict__ b_map,
                                float* __restrict__ out) {
    __shared__ float os[BB][192];
    int t = threadIdx.x;
    for (int idx = t; idx < BB*192; idx += 256) {
        int b = idx / 192, c = idx % 192;
        int l = c >> 6, d = c & 63;
        float m = -FLT_MAX;
        #pragma unroll
        for (int s = 0; s < 8; s++)
            m = fmaxf(m, g_pmax[((l*8 + s)*BB + b)*DH + d]);
        os[b][c] = m;
        out[idx] = m;                     // output block: [8][192]
    }
    __syncthreads();
    for (int idx = t; idx < BB*DH; idx += 256) {
        int b = idx >> 6, e = idx & 63;
        float a = b_map[e];
        #pragma unroll 4
        for (int k = 0; k < 192; k++)
            a = fmaf(os[b][k], w_map[k*DH + e], a);
        out[BB*192 + idx] = a;            // ypred block: [8][64]
    }
}

// ---------------- launch ----------------
extern "C" void kernel_launch(void* const* d_in, const int* in_sizes, int n_in,
                              void* d_out, int out_size) {
    const float* x       = (const float*)d_in[0];
    const int*   rel     = (const int*)  d_in[1];
    const float* w_first = (const float*)d_in[3];
    const float* b_first = (const float*)d_in[4];
    const float* w_block = (const float*)d_in[5];
    const float* b_block = (const float*)d_in[6];
    const float* w_last  = (const float*)d_in[7];
    const float* b_last  = (const float*)d_in[8];
    const float* w_map   = (const float*)d_in[9];
    const float* b_map   = (const float*)d_in[10];
    float* out = (float*)d_out;

    const int smem3 = 2*3*64*64*4;   // 98304 B (double-buffered)
    const int smem1 = 2*1*64*64*4;   // 32768 B
    cudaFuncSetAttribute(agg_kernel<3,true>,  cudaFuncAttributeMaxDynamicSharedMemorySize, smem3);
    cudaFuncSetAttribute(agg_kernel<1,true>,  cudaFuncAttributeMaxDynamicSharedMemorySize, smem1);
    cudaFuncSetAttribute(agg_kernel<1,false>, cudaFuncAttributeMaxDynamicSharedMemorySize, smem1);

    pack_rel_kernel<<<(BB*NN*NW + 255)/256, 256>>>(rel);
    xw_first_kernel<<<BB*NN/32, 192>>>(x, w_first);

    // layer 1
    agg_kernel<3,true><<<BB*16, 256, smem3>>>(b_first);
    bn_stats_kernel<<<NN, 256>>>();
    bn_apply_max_kernel<true><<<BB*8, 256>>>(0);

    // layer 2
    hw_kernel<<<BB*NN/4, 256>>>(w_block);
    agg_kernel<1,true><<<BB*16, 256, smem1>>>(b_block);
    bn_stats_kernel<<<NN, 256>>>();
    bn_apply_max_kernel<true><<<BB*8, 256>>>(1);

    // layer 3 (conv_last: no relu, no BN)
    hw_kernel<<<BB*NN/4, 256>>>(w_last);
    agg_kernel<1,false><<<BB*16, 256, smem1>>>(b_last);
    bn_apply_max_kernel<false><<<BB*8, 256>>>(2);

    finalize_kernel<<<1, 256>>>(w_map, b_map, out);
}

// round 4
// speedup vs baseline: 1.2648x; 1.1069x over previous
#include <cuda_runtime.h>
#include <cuda_bf16.h>
#include <cstdint>
#include <cfloat>

#define BB   8
#define NN   2048
#define DIN  32
#define DH   64
#define NW   (NN/16)          // 128 packed 2-bit label words per row
#define XWS  (BB*NN*DH)       // per-relation stride in g_xw

// ---------------- device scratch (no allocs allowed) ----------------
__device__ uint32_t g_relp[BB*NN*NW];     // packed relation labels (2 bit), 8.4 MB
__device__ float    g_xw [3*XWS];         // per-relation x@W, tf32-rounded, d-PERMUTED
__device__ float    g_part[2][BB*NN*DH];  // k-split partial sums
__device__ float    g_hn [BB*NN*DH];      // post-BN (input to next layer)
__device__ unsigned g_pmaxU[3*BB*DH];     // [layer][b][d], order-preserving uint keys

// d-axis permutation applied to g_xw so B-fragments are LDS.128-contiguous
__device__ __forceinline__ int perm_d(int d) { return ((d & 7) << 3) | (d >> 3); }
// per-row 16B-chunk XOR swizzle (values {0,1,4,5}) for bank-conflict freedom
__device__ __forceinline__ int swz(int row) { return (row & 1) | ((row & 2) << 1); }

// order-preserving float->uint key (monotonic; exact max)
__device__ __forceinline__ unsigned fkey(float f) {
    unsigned u = __float_as_uint(f);
    return (u & 0x80000000u) ? ~u : (u | 0x80000000u);
}
__device__ __forceinline__ float fdec(unsigned k) {
    unsigned u = (k & 0x80000000u) ? (k ^ 0x80000000u) : ~k;
    return __uint_as_float(u);
}

// ---------------- helpers ----------------
__device__ __forceinline__ float to_tf32(float v) {
    uint32_t t; asm("cvt.rna.tf32.f32 %0, %1;" : "=r"(t) : "f"(v));
    return __uint_as_float(t);
}

__device__ __forceinline__ void mma_tf32_k8(float c[4],
                                            uint32_t a0, uint32_t a1, uint32_t a2, uint32_t a3,
                                            uint32_t b0, uint32_t b1) {
    asm volatile(
        "mma.sync.aligned.m16n8k8.row.col.f32.tf32.tf32.f32 "
        "{%0,%1,%2,%3}, {%4,%5,%6,%7}, {%8,%9}, {%0,%1,%2,%3};\n"
        : "+f"(c[0]), "+f"(c[1]), "+f"(c[2]), "+f"(c[3])
        : "r"(a0), "r"(a1), "r"(a2), "r"(a3), "r"(b0), "r"(b1));
}

__device__ __forceinline__ void cp_async16(uint32_t dst, const void* src) {
    asm volatile("cp.async.cg.shared.global [%0], [%1], 16;\n"
                 :: "r"(dst), "l"(src) : "memory");
}
__device__ __forceinline__ void cp_commit() {
    asm volatile("cp.async.commit_group;\n" ::: "memory");
}
template<int N>
__device__ __forceinline__ void cp_wait() {
    asm volatile("cp.async.wait_group %0;\n" :: "n"(N) : "memory");
}

// ---------------- pack relation labels to 2 bits (+ init pmax keys) ----------------
__global__ void pack_rel_kernel(const int* __restrict__ rel) {
    int idx = blockIdx.x * blockDim.x + threadIdx.x;   // word index
    if (idx < 3*BB*DH) g_pmaxU[idx] = 0u;              // key 0 == -inf
    if (idx >= BB*NN*NW) return;
    const int4* p = (const int4*)(rel + (size_t)idx * 16);
    uint32_t wv = 0;
    #pragma unroll
    for (int q = 0; q < 4; q++) {
        int4 v = p[q];
        wv |= (uint32_t)(v.x & 3) << (8*q + 0);
        wv |= (uint32_t)(v.y & 3) << (8*q + 2);
        wv |= (uint32_t)(v.z & 3) << (8*q + 4);
        wv |= (uint32_t)(v.w & 3) << (8*q + 6);
    }
    g_relp[idx] = wv;
}

// ---------------- xw_r = x @ W_first[r], tf32, d-permuted; 32 rows/block ----------------
__global__ void xw_first_kernel(const float* __restrict__ x, const float* __restrict__ w) {
    __shared__ float ws[3*DIN*DH];   // 24 KB
    __shared__ float xs[32][DIN];    // 4 KB
    const int t = threadIdx.x;       // 192 threads
    const int row0 = blockIdx.x * 32;
    for (int i = t; i < 3*DIN*DH; i += 192) ws[i] = w[i];
    for (int i = t; i < 32*DIN; i += 192)
        xs[i >> 5][i & 31] = x[(size_t)row0*DIN + i];
    __syncthreads();
    const int r = t >> 6, d = t & 63;
    const int pd = perm_d(d);
    #pragma unroll 4
    for (int rr = 0; rr < 32; rr++) {
        float acc = 0.f;
        #pragma unroll
        for (int k = 0; k < DIN; k++)
            acc = fmaf(xs[rr][k], ws[(r*DIN + k)*DH + d], acc);
        g_xw[(size_t)r*XWS + (size_t)(row0 + rr)*DH + pd] = to_tf32(acc);
    }
}

// ---------------- xw = hn @ W[0]  (64x64), tf32, d-permuted ----------------
__global__ void hw_kernel(const float* __restrict__ w) {
    __shared__ float ws[DH*DH];            // 16 KB
    __shared__ float hs[4][DH];
    int t = threadIdx.x;
    for (int idx = t; idx < DH*DH/4; idx += 256)
        ((float4*)ws)[idx] = ((const float4*)w)[idx];
    int lr = t >> 6, d = t & 63;
    int row = blockIdx.x*4 + lr;
    hs[lr][d] = g_hn[(size_t)row*DH + d];
    __syncthreads();
    float acc = 0.f;
    #pragma unroll
    for (int k = 0; k < DH; k++)
        acc = fmaf(hs[lr][k], ws[k*DH + d], acc);
    g_xw[(size_t)row*DH + perm_d(d)] = to_tf32(acc);
}

// ---------------- masked aggregation GEMM, k-split, raw partial output ----------------
// grid: BB*16*2 (b, 128-row tile, k-half). block 256 = 8 warps, each m16 x n64.
// 32-row chunks, double-buffered cp.async; 2 CTAs/SM.
template<int NREL>
__global__ __launch_bounds__(256, 2) void agg_kernel() {
    extern __shared__ float Bs[];          // [2][NREL][32 rows][64 floats]
    const uint32_t sbase = (uint32_t)__cvta_generic_to_shared(Bs);
    const int BUFF = NREL * 32 * 64;       // floats per buffer

    const int bx = blockIdx.x;
    const int kh = bx & 1;
    const int i0 = ((bx >> 1) & 15) << 7;
    const int b  = bx >> 5;
    const int t = threadIdx.x;
    const int w = t >> 5, lane = t & 31, g = lane >> 2, tig = lane & 3;

    const int iA = i0 + w*16 + g;
    const uint32_t* rpA = g_relp + (size_t)(b*NN + iA) * NW + kh*64;
    const uint32_t* rpB = rpA + 8*NW;

    // staging decomposition (thread-constant): NREL*2 cp.async of 16B per chunk
    uint32_t st_dst[NREL*2];
    int      st_off[NREL*2];               // float offset into g_xw for chunk 0
    #pragma unroll
    for (int s = 0; s < NREL*2; s++) {
        int it  = s*256 + t;               // < NREL*512
        int rel = it >> 9;
        int rem = it & 511;
        int kk  = rem >> 4, c4 = rem & 15;
        st_dst[s] = sbase + (uint32_t)((rel*2048 + kk*64 + ((c4 ^ swz(kk & 3)) << 2)) << 2);
        st_off[s] = rel*XWS + (b*NN + kh*1024 + kk)*DH + (c4 << 2);
    }

    float acc[8][4];
    #pragma unroll
    for (int nt = 0; nt < 8; nt++)
        #pragma unroll
        for (int q = 0; q < 4; q++) acc[nt][q] = 0.f;

    const uint32_t ONE = 0x3F800000u;

    // prologue: stage chunk 0; preload labels
    #pragma unroll
    for (int s = 0; s < NREL*2; s++)
        cp_async16(st_dst[s], g_xw + st_off[s]);
    cp_commit();
    uint2 LA = *(const uint2*)(rpA);
    uint2 LB = *(const uint2*)(rpB);

    for (int c = 0; c < 32; c++) {
        const int cb = c & 1;
        if (c + 1 < 32) {
            const uint32_t doff = (uint32_t)(((c + 1) & 1) * BUFF) << 2;
            const int goff = (c + 1) * 32 * DH;
            #pragma unroll
            for (int s = 0; s < NREL*2; s++)
                cp_async16(st_dst[s] + doff, g_xw + st_off[s] + goff);
            cp_commit();
            cp_wait<1>();
        } else {
            cp_wait<0>();
        }
        __syncthreads();

        uint32_t wA[2] = {LA.x, LA.y};
        uint32_t wB[2] = {LB.x, LB.y};
        if (c + 1 < 32) {
            LA = *(const uint2*)(rpA + (c + 1) * 2);
            LB = *(const uint2*)(rpB + (c + 1) * 2);
        }

        const float* bufp = Bs + cb * BUFF;
        const int sw = swz(tig);
        const int ch0 = (2*g) ^ sw, ch1 = (2*g + 1) ^ sw;

        #pragma unroll
        for (int s8 = 0; s8 < 4; s8++) {
            const int wi   = s8 >> 1;
            const int base = 16*(s8 & 1) + 2*tig;
            uint32_t labA0 = (wA[wi] >> base) & 3;
            uint32_t labA1 = (wA[wi] >> (base + 8)) & 3;
            uint32_t labB0 = (wB[wi] >> base) & 3;
            uint32_t labB1 = (wB[wi] >> (base + 8)) & 3;
            const int row0 = s8*8 + tig;
            #pragma unroll
            for (int r = 0; r < NREL; r++) {
                uint32_t a0, a1, a2, a3;
                if (NREL == 1) {
                    a0 = labA0 ? ONE : 0u; a1 = labB0 ? ONE : 0u;
                    a2 = labA1 ? ONE : 0u; a3 = labB1 ? ONE : 0u;
                } else {
                    a0 = (labA0 == (uint32_t)(r+1)) ? ONE : 0u;
                    a1 = (labB0 == (uint32_t)(r+1)) ? ONE : 0u;
                    a2 = (labA1 == (uint32_t)(r+1)) ? ONE : 0u;
                    a3 = (labB1 == (uint32_t)(r+1)) ? ONE : 0u;
                }
                const float* rb = bufp + r*2048;
                float4 B0a = *(const float4*)(rb + row0*64       + (ch0 << 2));
                float4 B0b = *(const float4*)(rb + row0*64       + (ch1 << 2));
                float4 B1a = *(const float4*)(rb + (row0+4)*64   + (ch0 << 2));
                float4 B1b = *(const float4*)(rb + (row0+4)*64   + (ch1 << 2));
                const float b0v[8] = {B0a.x,B0a.y,B0a.z,B0a.w, B0b.x,B0b.y,B0b.z,B0b.w};
                const float b1v[8] = {B1a.x,B1a.y,B1a.z,B1a.w, B1b.x,B1b.y,B1b.z,B1b.w};
                #pragma unroll
                for (int nt = 0; nt < 8; nt++)
                    mma_tf32_k8(acc[nt], a0, a1, a2, a3,
                                __float_as_uint(b0v[nt]), __float_as_uint(b1v[nt]));
            }
        }
        __syncthreads();
    }

    // store raw partials
    float* outA = g_part[kh] + (size_t)(b*NN + iA)*DH;
    float* outB = outA + 8*DH;
    #pragma unroll
    for (int nt = 0; nt < 8; nt++) {
        *(float2*)(outA + nt*8 + 2*tig) = make_float2(acc[nt][0], acc[nt][1]);
        *(float2*)(outB + nt*8 + 2*tig) = make_float2(acc[nt][2], acc[nt][3]);
    }
}

// ---------------- combine (BN layers): partials+bias -> L2norm -> relu -> BN -> max ----
// block = node-chunk of 8 i's; warp w <-> batch b=w; lane l <-> d = {2l, 2l+1}.
__global__ __launch_bounds__(256) void combine_bn_kernel(const float* __restrict__ bias, int L) {
    __shared__ float2 ys[8][256];      // [ii][w*32+l]
    __shared__ float2 sums[8][8];      // [ii][warp] (sum, sumsq)
    __shared__ float2 stats[8];        // (mean, rstd)
    const int t = threadIdx.x, w = t >> 5, l = t & 31;
    const int i0 = blockIdx.x * 8;
    const float2 bv = ((const float2*)bias)[l];

    #pragma unroll
    for (int ii = 0; ii < 8; ii++) {
        const size_t off = ((size_t)w*NN + (i0 + ii))*DH + 2*l;
        float2 p0 = *(const float2*)(g_part[0] + off);
        float2 p1 = *(const float2*)(g_part[1] + off);
        float y0 = p0.x + p1.x + bv.x;
        float y1 = p0.y + p1.y + bv.y;
        float s = y0*y0 + y1*y1;
        #pragma unroll
        for (int o = 16; o > 0; o >>= 1) s += __shfl_xor_sync(0xffffffffu, s, o);
        float sc = 1.f / fmaxf(sqrtf(s), 1e-12f);
        y0 = fmaxf(y0*sc, 0.f); y1 = fmaxf(y1*sc, 0.f);
        ys[ii][w*32 + l] = make_float2(y0, y1);
        float ss = y0 + y1, sq = y0*y0 + y1*y1;
        #pragma unroll
        for (int o = 16; o > 0; o >>= 1) {
            ss += __shfl_xor_sync(0xffffffffu, ss, o);
            sq += __shfl_xor_sync(0xffffffffu, sq, o);
        }
        if (l == 0) sums[ii][w] = make_float2(ss, sq);
    }
    __syncthreads();
    if (t < 8) {
        float S = 0.f, Q = 0.f;
        #pragma unroll
        for (int k = 0; k < 8; k++) { S += sums[t][k].x; Q += sums[t][k].y; }
        float m = S * (1.f/512.f);
        stats[t] = make_float2(m, rsqrtf(Q * (1.f/512.f) - m*m + 1e-5f));
    }
    __syncthreads();
    float m0 = -FLT_MAX, m1 = -FLT_MAX;
    #pragma unroll
    for (int ii = 0; ii < 8; ii++) {
        float2 y = ys[ii][w*32 + l];
        float2 st = stats[ii];
        float z0 = (y.x - st.x) * st.y;
        float z1 = (y.y - st.x) * st.y;
        *(float2*)(g_hn + ((size_t)w*NN + (i0 + ii))*DH + 2*l) = make_float2(z0, z1);
        m0 = fmaxf(m0, z0); m1 = fmaxf(m1, z1);
    }
    atomicMax(&g_pmaxU[(L*BB + w)*DH + 2*l    ], fkey(m0));
    atomicMax(&g_pmaxU[(L*BB + w)*DH + 2*l + 1], fkey(m1));
}

// ---------------- combine (last layer): partials+bias -> L2norm -> max ----------------
__global__ __launch_bounds__(256) void combine_last_kernel(const float* __restrict__ bias) {
    const int t = threadIdx.x, w = t >> 5, l = t & 31;
    const int i0 = blockIdx.x * 8;
    const float2 bv = ((const float2*)bias)[l];
    float m0 = -FLT_MAX, m1 = -FLT_MAX;
    #pragma unroll
    for (int ii = 0; ii < 8; ii++) {
        const size_t off = ((size_t)w*NN + (i0 + ii))*DH + 2*l;
        float2 p0 = *(const float2*)(g_part[0] + off);
        float2 p1 = *(const float2*)(g_part[1] + off);
        float y0 = p0.x + p1.x + bv.x;
        float y1 = p0.y + p1.y + bv.y;
        float s = y0*y0 + y1*y1;
        #pragma unroll
        for (int o = 16; o > 0; o >>= 1) s += __shfl_xor_sync(0xffffffffu, s, o);
        float sc = 1.f / fmaxf(sqrtf(s), 1e-12f);
        m0 = fmaxf(m0, y0*sc); m1 = fmaxf(m1, y1*sc);
    }
    atomicMax(&g_pmaxU[(2*BB + w)*DH + 2*l    ], fkey(m0));
    atomicMax(&g_pmaxU[(2*BB + w)*DH + 2*l + 1], fkey(m1));
}

// ---------------- finalize: decode maxes, concat, final linear ----------------
__global__ void finalize_kernel(const float* __restrict__ w_map,
                                const float* __restrict__ b_map,
                                float* __restrict__ out) {
    __shared__ float os[BB][192];
    int t = threadIdx.x;
    for (int idx = t; idx < BB*192; idx += 256) {
        int b = idx / 192, c = idx % 192;
        int l = c >> 6, d = c & 63;
        float m = fdec(g_pmaxU[(l*BB + b)*DH + d]);
        os[b][c] = m;
        out[idx] = m;                     // output block: [8][192]
    }
    __syncthreads();
    for (int idx = t; idx < BB*DH; idx += 256) {
        int b = idx >> 6, e = idx & 63;
        float a = b_map[e];
        #pragma unroll 4
        for (int k = 0; k < 192; k++)
            a = fmaf(os[b][k], w_map[k*DH + e], a);
        out[BB*192 + idx] = a;            // ypred block: [8][64]
    }
}

// ---------------- launch ----------------
extern "C" void kernel_launch(void* const* d_in, const int* in_sizes, int n_in,
                              void* d_out, int out_size) {
    const float* x       = (const float*)d_in[0];
    const int*   rel     = (const int*)  d_in[1];
    const float* w_first = (const float*)d_in[3];
    const float* b_first = (const float*)d_in[4];
    const float* w_block = (const float*)d_in[5];
    const float* b_block = (const float*)d_in[6];
    const float* w_last  = (const float*)d_in[7];
    const float* b_last  = (const float*)d_in[8];
    const float* w_map   = (const float*)d_in[9];
    const float* b_map   = (const float*)d_in[10];
    float* out = (float*)d_out;

    const int smem3 = 2*3*32*64*4;   // 49152 B
    const int smem1 = 2*1*32*64*4;   // 16384 B
    cudaFuncSetAttribute(agg_kernel<3>, cudaFuncAttributeMaxDynamicSharedMemorySize, smem3);
    cudaFuncSetAttribute(agg_kernel<1>, cudaFuncAttributeMaxDynamicSharedMemorySize, smem1);

    pack_rel_kernel<<<(BB*NN*NW + 255)/256, 256>>>(rel);
    xw_first_kernel<<<BB*NN/32, 192>>>(x, w_first);

    // layer 1
    agg_kernel<3><<<BB*16*2, 256, smem3>>>();
    combine_bn_kernel<<<NN/8, 256>>>(b_first, 0);

    // layer 2
    hw_kernel<<<BB*NN/4, 256>>>(w_block);
    agg_kernel<1><<<BB*16*2, 256, smem1>>>();
    combine_bn_kernel<<<NN/8, 256>>>(b_block, 1);

    // layer 3 (conv_last: no relu, no BN)
    hw_kernel<<<BB*NN/4, 256>>>(w_last);
    agg_kernel<1><<<BB*16*2, 256, smem1>>>();
    combine_last_kernel<<<NN/8, 256>>>(b_last);

    finalize_kernel<<<1, 256>>>(w_map, b_map, out);
}